// round 11
// baseline (speedup 1.0000x reference)
#include <cuda_runtime.h>
#include <cuda_bf16.h>
#include <math.h>
#include <stdint.h>

#define B_ 8
#define S_ 2048
#define D_ 1024
#define H_ 64
#define BS_ (B_*S_)

// log2(e) / sqrt(D)
#define QSCALE 0.0450842200277801f

// ---------------------------------------------------------------------------
// Globals
// ---------------------------------------------------------------------------
__device__ __nv_bfloat16 g_qh[BS_ * H_], g_ql[BS_ * H_];
__device__ __nv_bfloat16 g_kh[BS_ * H_], g_kl[BS_ * H_];
__device__ __nv_bfloat16 g_vh[BS_ * H_], g_vl[BS_ * H_];
__device__ __nv_bfloat16 g_wth[192 * D_], g_wtl[192 * D_];
// split-K partials: [half][b][s][h] unnormalized O, [half][b][s] lsum
__device__ float g_po[2 * BS_ * H_];
__device__ float g_pl[2 * BS_];

// ---------------------------------------------------------------------------
// PTX helpers (sm_80-era — safe under compute_100)
// ---------------------------------------------------------------------------
__device__ __forceinline__ uint32_t smem_u32(const void* p) {
    uint32_t a;
    asm("{ .reg .u64 t; cvta.to.shared.u64 t, %1; cvt.u32.u64 %0, t; }" : "=r"(a) : "l"(p));
    return a;
}
__device__ __forceinline__ void ldsm4(uint32_t* r, uint32_t addr) {
    asm volatile("ldmatrix.sync.aligned.m8n8.x4.shared.b16 {%0,%1,%2,%3}, [%4];"
                 : "=r"(r[0]), "=r"(r[1]), "=r"(r[2]), "=r"(r[3]) : "r"(addr));
}
__device__ __forceinline__ void ldsm4t(uint32_t* r, uint32_t addr) {
    asm volatile("ldmatrix.sync.aligned.m8n8.x4.trans.shared.b16 {%0,%1,%2,%3}, [%4];"
                 : "=r"(r[0]), "=r"(r[1]), "=r"(r[2]), "=r"(r[3]) : "r"(addr));
}
__device__ __forceinline__ void mma_bf16(float* c, const uint32_t* a, const uint32_t* b) {
    asm volatile(
        "mma.sync.aligned.m16n8k16.row.col.f32.bf16.bf16.f32 "
        "{%0,%1,%2,%3}, {%4,%5,%6,%7}, {%8,%9}, {%0,%1,%2,%3};"
        : "+f"(c[0]), "+f"(c[1]), "+f"(c[2]), "+f"(c[3])
        : "r"(a[0]), "r"(a[1]), "r"(a[2]), "r"(a[3]), "r"(b[0]), "r"(b[1]));
}
__device__ __forceinline__ uint32_t pack_bf16_hi(float x, float y) {
    __nv_bfloat162 h = make_bfloat162(__float2bfloat16(x), __float2bfloat16(y));
    return *(uint32_t*)&h;
}
__device__ __forceinline__ uint32_t prmt7632(uint32_t a, uint32_t b) {
    uint32_t d; asm("prmt.b32 %0, %1, %2, 0x7632;" : "=r"(d) : "r"(a), "r"(b)); return d;
}
__device__ __forceinline__ uint32_t cvt_bf16x2(float hi, float lo) {
    uint32_t d; asm("cvt.rn.bf16x2.f32 %0, %1, %2;" : "=r"(d) : "f"(hi), "f"(lo)); return d;
}
__device__ __forceinline__ float ex2f(float x) {
    float r; asm("ex2.approx.f32 %0, %1;" : "=f"(r) : "f"(x)); return r;
}
__device__ __forceinline__ void cpa16(uint32_t dst, const void* src) {
    asm volatile("cp.async.cg.shared.global [%0], [%1], 16;" :: "r"(dst), "l"(src));
}
#define CP_COMMIT() asm volatile("cp.async.commit_group;" ::: "memory")
#define CP_WAIT(n)  asm volatile("cp.async.wait_group %0;" :: "n"(n) : "memory")

__device__ __forceinline__ void store_split(__nv_bfloat16* Ah, __nv_bfloat16* Al,
                                            size_t idx, float x, float y) {
    __nv_bfloat16 hx = __float2bfloat16(x), hy = __float2bfloat16(y);
    __nv_bfloat162 hi = make_bfloat162(hx, hy);
    __nv_bfloat162 lo = make_bfloat162(__float2bfloat16(x - __bfloat162float(hx)),
                                       __float2bfloat16(y - __bfloat162float(hy)));
    *(uint32_t*)(Ah + idx) = *(uint32_t*)&hi;
    *(uint32_t*)(Al + idx) = *(uint32_t*)&lo;
}

// ---------------------------------------------------------------------------
// Kernel 0: transpose + bf16-split weights
// ---------------------------------------------------------------------------
__global__ __launch_bounds__(256) void wconv_kernel(
    const float* __restrict__ Wq, const float* __restrict__ Wk,
    const float* __restrict__ Wv)
{
    int n = blockIdx.x;
    const float* W = (n < 64) ? Wq : (n < 128 ? Wk : Wv);
    int col = n & 63;
    for (int k = threadIdx.x; k < D_; k += 256) {
        float x = W[(size_t)k * H_ + col];
        __nv_bfloat16 h = __float2bfloat16(x);
        g_wth[n * D_ + k] = h;
        g_wtl[n * D_ + k] = __float2bfloat16(x - __bfloat162float(h));
    }
}

// ---------------------------------------------------------------------------
// Kernel 1: QKV via mma.sync bf16-split, M=64 tiles (R8-proven: 2 CTAs/SM).
// CTA: 64x192, K-chunks of 32, double-buffered. 8 warps (2x4), warp 32x48.
// ---------------------------------------------------------------------------
#define QROWB 80
#define QXTILE (64 * QROWB)      // 5120
#define QWTILE (192 * QROWB)     // 15360
#define QOFF_XH 0
#define QOFF_XL QXTILE
#define QOFF_WH (2 * QXTILE)
#define QOFF_WL (2 * QXTILE + QWTILE)
#define QSTAGE  (2 * QXTILE + 2 * QWTILE)   // 40960
#define QKV_SMEM_BYTES (2 * QSTAGE)         // 81920

extern __shared__ char qkv_sm[];

__global__ __launch_bounds__(256) void qkv_mma_kernel(const float* __restrict__ X)
{
    const int t = threadIdx.x;
    const int lane = t & 31;
    const int w = t >> 5;
    const int m_w = (w & 1) * 32;
    const int n_w = (w >> 1) * 48;
    const int row0 = blockIdx.x * 64;
    const uint32_t sb = smem_u32(qkv_sm);

    float C[2][6][4];
#pragma unroll
    for (int mf = 0; mf < 2; mf++)
#pragma unroll
        for (int nf = 0; nf < 6; nf++)
#pragma unroll
            for (int i = 0; i < 4; i++) C[mf][nf][i] = 0.f;

    const int x_row[2] = { t >> 3, (t + 256) >> 3 };
    const int x_kq     = (t & 7) << 2;
    const float* Xb = X + (size_t)row0 * D_;

    auto lda = [&](int c, float4* xr) {
        int k0 = c * 32;
#pragma unroll
        for (int j = 0; j < 2; j++)
            xr[j] = __ldg((const float4*)(Xb + (size_t)x_row[j] * D_ + k0 + x_kq));
    };
    auto stx = [&](int s, const float4* xr) {
        char* stage = qkv_sm + s * QSTAGE;
#pragma unroll
        for (int j = 0; j < 2; j++) {
            float4 x = xr[j];
            float hx = __bfloat162float(__float2bfloat16(x.x));
            float hy = __bfloat162float(__float2bfloat16(x.y));
            float hz = __bfloat162float(__float2bfloat16(x.z));
            float hw = __bfloat162float(__float2bfloat16(x.w));
            uint2 hi = make_uint2(pack_bf16_hi(x.x, x.y), pack_bf16_hi(x.z, x.w));
            uint2 lo = make_uint2(pack_bf16_hi(x.x - hx, x.y - hy),
                                  pack_bf16_hi(x.z - hz, x.w - hw));
            int off = x_row[j] * QROWB + x_kq * 2;
            *(uint2*)(stage + QOFF_XH + off) = hi;
            *(uint2*)(stage + QOFF_XL + off) = lo;
        }
    };
    auto ldw = [&](int s, int c) {
        int k0 = c * 32;
        uint32_t base = sb + s * QSTAGE;
#pragma unroll
        for (int j = 0; j < 6; j++) {
            int i    = t + 256 * j;
            int half = i / 768;
            int rem  = i - half * 768;
            int row  = rem >> 2;
            int c16  = (rem & 3) << 4;
            const char* src = (const char*)(half ? g_wtl : g_wth)
                              + (size_t)row * (D_ * 2) + k0 * 2 + c16;
            cpa16(base + (half ? QOFF_WL : QOFF_WH) + row * QROWB + c16, src);
        }
        CP_COMMIT();
    };

    const int a_row = lane & 15;
    const int a_kb  = (lane >> 4) * 16;
    const int b_row = (lane & 7) + ((lane >> 4) & 1) * 8;
    const int b_kb  = ((lane >> 3) & 1) * 16;

    {
        float4 xr[2];
        lda(0, xr);
        ldw(0, 0);
        stx(0, xr);
    }
    CP_WAIT(0);
    __syncthreads();

    for (int c = 0; c < 32; c++) {
        const int s = c & 1;
        float4 xn[2];
        if (c + 1 < 32) {
            lda(c + 1, xn);
            ldw(s ^ 1, c + 1);
        }

        const uint32_t xh_b = sb + s * QSTAGE + QOFF_XH;
        const uint32_t xl_b = sb + s * QSTAGE + QOFF_XL;
        const uint32_t wh_b = sb + s * QSTAGE + QOFF_WH;
        const uint32_t wl_b = sb + s * QSTAGE + QOFF_WL;

#pragma unroll
        for (int kk = 0; kk < 2; kk++) {
            const int kb = kk * 32;
            uint32_t Ah[2][4], Al[2][4], Bh[3][4], Bl[3][4];
#pragma unroll
            for (int mf = 0; mf < 2; mf++) {
                uint32_t off = (uint32_t)((m_w + mf * 16 + a_row) * QROWB + kb + a_kb);
                ldsm4(Ah[mf], xh_b + off);
                ldsm4(Al[mf], xl_b + off);
            }
#pragma unroll
            for (int np = 0; np < 3; np++) {
                uint32_t off = (uint32_t)((n_w + np * 16 + b_row) * QROWB + kb + b_kb);
                ldsm4(Bh[np], wh_b + off);
                ldsm4(Bl[np], wl_b + off);
            }
#pragma unroll
            for (int mf = 0; mf < 2; mf++)
#pragma unroll
                for (int np = 0; np < 3; np++) {
                    mma_bf16(C[mf][2*np],   Ah[mf], Bh[np]);
                    mma_bf16(C[mf][2*np],   Ah[mf], Bl[np]);
                    mma_bf16(C[mf][2*np],   Al[mf], Bh[np]);
                    mma_bf16(C[mf][2*np+1], Ah[mf], Bh[np] + 2);
                    mma_bf16(C[mf][2*np+1], Ah[mf], Bl[np] + 2);
                    mma_bf16(C[mf][2*np+1], Al[mf], Bh[np] + 2);
                }
        }

        if (c + 1 < 32) stx(s ^ 1, xn);
        CP_WAIT(0);
        __syncthreads();
    }

#pragma unroll
    for (int mf = 0; mf < 2; mf++)
#pragma unroll
        for (int nf = 0; nf < 6; nf++) {
            int gr = row0 + m_w + mf * 16 + (lane >> 2);
            int gc = n_w + nf * 8 + (lane & 3) * 2;
            __nv_bfloat16 *Ah, *Al;
            float sc;
            int h;
            if (gc < 64)       { Ah = g_qh; Al = g_ql; sc = QSCALE; h = gc; }
            else if (gc < 128) { Ah = g_kh; Al = g_kl; sc = 1.f;    h = gc - 64; }
            else               { Ah = g_vh; Al = g_vl; sc = 1.f;    h = gc - 128; }
            store_split(Ah, Al, (size_t)gr * H_ + h,
                        C[mf][nf][0] * sc, C[mf][nf][1] * sc);
            store_split(Ah, Al, (size_t)(gr + 8) * H_ + h,
                        C[mf][nf][2] * sc, C[mf][nf][3] * sc);
        }
}

// ---------------------------------------------------------------------------
// Kernel 2: causal flash attention, split-K, Q aliased into KV stage 1.
// SMEM = 2 stages only (72 KB) -> 3 CTAs/SM, 384-CTA grid = single wave.
// Q occupies the first 2*TILEB of stage 1; consumed into registers (plus a
// CTA barrier) before stage 1 is first written.
// ---------------------------------------------------------------------------
#define ROWB 144
#define TILEB (64 * ROWB)            // 9216
#define STAGEB (4 * TILEB)           // 36864 (Kh,Kl,Vh,Vl)
#define OFF_QH STAGEB                // alias: start of stage 1
#define OFF_QL (STAGEB + TILEB)
#define ATTN_SMEM_BYTES (2 * STAGEB) // 73728

extern __shared__ char attn_sm[];

__global__ __launch_bounds__(128, 3) void attn_kernel(float* __restrict__ out)
{
    const int bid  = blockIdx.x;
    const int u    = bid >> 3;
    const int b    = bid & 7;
    int qt, kt0, kt1, half;
    bool split;
    if (u < 32) {                       // halves of qt 31..16, heavy first
        qt = 31 - (u >> 1);
        half = u & 1;
        split = true;
        int n = qt + 1, mid = n >> 1;
        kt0 = half ? mid : 0;
        kt1 = half ? n : mid;
    } else {                            // singles qt 15..0
        qt = 47 - u;
        half = 0;
        split = false;
        kt0 = 0;
        kt1 = qt + 1;
    }

    const int t    = threadIdx.x;
    const int w    = t >> 5;
    const int lane = t & 31;
    const int m_w  = w * 16;

    const uint32_t sb = smem_u32(attn_sm);
    const size_t qoff = ((size_t)b * S_ + (size_t)qt * 64) * H_;

    {
        const char* qsrc[2] = { (const char*)(g_qh + qoff), (const char*)(g_ql + qoff) };
#pragma unroll
        for (int j = 0; j < 8; j++) {
            int i   = t + 128 * j;
            int arr = i >> 9;
            int rem = i & 511;
            int row = rem >> 3;
            int c16 = (rem & 7) << 4;
            cpa16(sb + (arr ? OFF_QL : OFF_QH) + row * ROWB + c16,
                  qsrc[arr] + row * 128 + c16);
        }
        CP_COMMIT();
    }
    auto load_kv = [&](int s, int kt) {
        size_t koff = ((size_t)b * S_ + (size_t)kt * 64) * H_;
        const char* srcs[4] = { (const char*)(g_kh + koff), (const char*)(g_kl + koff),
                                (const char*)(g_vh + koff), (const char*)(g_vl + koff) };
        uint32_t base = sb + s * STAGEB;
#pragma unroll
        for (int j = 0; j < 16; j++) {
            int i   = t + 128 * j;
            int arr = i >> 9;
            int rem = i & 511;
            int row = rem >> 3;
            int c16 = (rem & 7) << 4;
            cpa16(base + arr * TILEB + row * ROWB + c16,
                  srcs[arr] + row * 128 + c16);
        }
        CP_COMMIT();
    };
    load_kv(0, kt0);

    CP_WAIT(1);          // Q resident (stage-0 KV may still be in flight)
    __syncthreads();

    uint32_t QAh[4][4], QAl[4][4];
    {
        int qr = m_w + (lane & 7) + ((lane >> 3) & 1) * 8;
        int qb = (lane >> 4) * 16;
#pragma unroll
        for (int ks = 0; ks < 4; ks++) {
            ldsm4(QAh[ks], sb + OFF_QH + qr * ROWB + ks * 32 + qb);
            ldsm4(QAl[ks], sb + OFF_QL + qr * ROWB + ks * 32 + qb);
        }
    }
    __syncthreads();     // ALL warps have consumed Q before stage 1 is written

    float O[8][4];
#pragma unroll
    for (int nf = 0; nf < 8; nf++)
#pragma unroll
        for (int i = 0; i < 4; i++) O[nf][i] = 0.f;
    float lsum0 = 0.f, lsum1 = 0.f;

    const int qrow0 = qt * 64 + m_w + (lane >> 2);
    const int qrow1 = qrow0 + 8;
    const float NEGINF = __int_as_float(0xff800000);

    const int kb_row = (lane & 7) + ((lane >> 4) & 1) * 8;
    const int kb_byt = ((lane >> 3) & 1) * 16;
    const int vb_row = (lane & 7) + ((lane >> 3) & 1) * 8;
    const int vb_byt = ((lane >> 4) & 1) * 16;

    for (int kt = kt0; kt < kt1; kt++) {
        const int s = (kt - kt0) & 1;
        if (kt + 1 < kt1) { load_kv(s ^ 1, kt + 1); CP_WAIT(1); }
        else              { CP_WAIT(0); }
        __syncthreads();

        const uint32_t kh_b = sb + s * STAGEB;
        const uint32_t kl_b = kh_b + TILEB;
        const uint32_t vh_b = kh_b + 2 * TILEB;
        const uint32_t vl_b = kh_b + 3 * TILEB;

        float S[8][4];
#pragma unroll
        for (int nf = 0; nf < 8; nf++)
#pragma unroll
            for (int i = 0; i < 4; i++) S[nf][i] = 0.f;

#pragma unroll
        for (int ks = 0; ks < 4; ks++) {
#pragma unroll
            for (int g = 0; g < 4; g++) {
                uint32_t off = (uint32_t)((g * 16 + kb_row) * ROWB + ks * 32 + kb_byt);
                uint32_t bh[4], bl[4];
                ldsm4(bh, kh_b + off);
                ldsm4(bl, kl_b + off);
                mma_bf16(S[2*g],   QAh[ks], bh);
                mma_bf16(S[2*g],   QAh[ks], bl);
                mma_bf16(S[2*g],   QAl[ks], bh);
                mma_bf16(S[2*g+1], QAh[ks], bh + 2);
                mma_bf16(S[2*g+1], QAh[ks], bl + 2);
                mma_bf16(S[2*g+1], QAl[ks], bh + 2);
            }
        }

        const bool diag = (kt == qt);
        uint32_t Ph[4][4], Pl[4][4];
#pragma unroll
        for (int nf = 0; nf < 8; nf++) {
            float c0 = S[nf][0], c1 = S[nf][1], c2 = S[nf][2], c3 = S[nf][3];
            if (diag) {
                int key0 = kt * 64 + nf * 8 + (lane & 3) * 2;
                if (key0     > qrow0) c0 = NEGINF;
                if (key0 + 1 > qrow0) c1 = NEGINF;
                if (key0     > qrow1) c2 = NEGINF;
                if (key0 + 1 > qrow1) c3 = NEGINF;
            }
            float p0 = ex2f(c0), p1 = ex2f(c1), p2 = ex2f(c2), p3 = ex2f(c3);
            lsum0 += p0 + p1;
            lsum1 += p2 + p3;
            uint32_t u0 = __float_as_uint(p0), u1 = __float_as_uint(p1);
            uint32_t u2 = __float_as_uint(p2), u3 = __float_as_uint(p3);
            float r0 = p0 - __uint_as_float(u0 & 0xFFFF0000u);
            float r1 = p1 - __uint_as_float(u1 & 0xFFFF0000u);
            float r2 = p2 - __uint_as_float(u2 & 0xFFFF0000u);
            float r3 = p3 - __uint_as_float(u3 & 0xFFFF0000u);
            int ks = nf >> 1, hf = (nf & 1) * 2;
            Ph[ks][hf]     = prmt7632(u0, u1);
            Ph[ks][hf + 1] = prmt7632(u2, u3);
            Pl[ks][hf]     = cvt_bf16x2(r1, r0);
            Pl[ks][hf + 1] = cvt_bf16x2(r3, r2);
        }

#pragma unroll
        for (int ks = 0; ks < 4; ks++) {
#pragma unroll
            for (int g = 0; g < 4; g++) {
                uint32_t off = (uint32_t)((ks * 16 + vb_row) * ROWB + g * 32 + vb_byt);
                uint32_t vh[4], vl[4];
                ldsm4t(vh, vh_b + off);
                ldsm4t(vl, vl_b + off);
                mma_bf16(O[2*g],   Ph[ks], vh);
                mma_bf16(O[2*g],   Ph[ks], vl);
                mma_bf16(O[2*g],   Pl[ks], vh);
                mma_bf16(O[2*g+1], Ph[ks], vh + 2);
                mma_bf16(O[2*g+1], Ph[ks], vl + 2);
                mma_bf16(O[2*g+1], Pl[ks], vh + 2);
            }
        }
        __syncthreads();
    }

    lsum0 += __shfl_xor_sync(0xffffffffu, lsum0, 1);
    lsum0 += __shfl_xor_sync(0xffffffffu, lsum0, 2);
    lsum1 += __shfl_xor_sync(0xffffffffu, lsum1, 1);
    lsum1 += __shfl_xor_sync(0xffffffffu, lsum1, 2);

    const int gr0 = qt * 64 + m_w + (lane >> 2);
    if (split) {
        float* PO = g_po + (size_t)half * (BS_ * H_) + (size_t)b * S_ * H_;
        float* PL = g_pl + half * BS_ + b * S_;
        if ((lane & 3) == 0) {
            PL[gr0]     = lsum0;
            PL[gr0 + 8] = lsum1;
        }
#pragma unroll
        for (int nf = 0; nf < 8; nf++) {
            int h = nf * 8 + (lane & 3) * 2;
            *(float2*)(PO + (size_t)gr0 * H_ + h)       = make_float2(O[nf][0], O[nf][1]);
            *(float2*)(PO + (size_t)(gr0 + 8) * H_ + h) = make_float2(O[nf][2], O[nf][3]);
        }
    } else {
        float inv0 = 1.f / lsum0, inv1 = 1.f / lsum1;
        float* Ob = out + (size_t)b * S_ * H_;
#pragma unroll
        for (int nf = 0; nf < 8; nf++) {
            int h = nf * 8 + (lane & 3) * 2;
            *(float2*)(Ob + (size_t)gr0 * H_ + h) =
                make_float2(O[nf][0] * inv0, O[nf][1] * inv0);
            *(float2*)(Ob + (size_t)(gr0 + 8) * H_ + h) =
                make_float2(O[nf][2] * inv1, O[nf][3] * inv1);
        }
    }
}

// ---------------------------------------------------------------------------
// Kernel 3: merge split-K partials for rows 1024..2047 of each batch.
// ---------------------------------------------------------------------------
__global__ __launch_bounds__(256) void merge_kernel(float* __restrict__ out)
{
    int gi = blockIdx.x * 256 + threadIdx.x;
    int b   = gi >> 14;
    int rem = gi & 16383;
    int row = 1024 + (rem >> 4);
    int c4  = rem & 15;
    size_t off = ((size_t)b * S_ + row) * H_ + c4 * 4;
    float l = g_pl[b * S_ + row] + g_pl[BS_ + b * S_ + row];
    float inv = 1.f / l;
    float4 a0 = *(const float4*)(g_po + off);
    float4 a1 = *(const float4*)(g_po + (size_t)BS_ * H_ + off);
    float4 r;
    r.x = (a0.x + a1.x) * inv;
    r.y = (a0.y + a1.y) * inv;
    r.z = (a0.z + a1.z) * inv;
    r.w = (a0.w + a1.w) * inv;
    *(float4*)(out + off) = r;
}

// ---------------------------------------------------------------------------
// kernel_launch — graph-capturable, allocation-free.
// Input order (metadata): idx, Wk, Wq, Wv. Output: [8, 2048, 64] f32.
// ---------------------------------------------------------------------------
extern "C" void kernel_launch(void* const* d_in, const int* in_sizes, int n_in,
                              void* d_out, int out_size)
{
    const float* X  = (const float*)d_in[0];
    const float* Wk = (const float*)d_in[1];
    const float* Wq = (const float*)d_in[2];
    const float* Wv = (const float*)d_in[3];
    float* out = (float*)d_out;

    wconv_kernel<<<192, 256>>>(Wq, Wk, Wv);

    cudaFuncSetAttribute(qkv_mma_kernel,
                         cudaFuncAttributeMaxDynamicSharedMemorySize,
                         QKV_SMEM_BYTES);
    qkv_mma_kernel<<<BS_ / 64, 256, QKV_SMEM_BYTES>>>(X);

    cudaFuncSetAttribute(attn_kernel,
                         cudaFuncAttributeMaxDynamicSharedMemorySize,
                         ATTN_SMEM_BYTES);
    attn_kernel<<<384, 128, ATTN_SMEM_BYTES>>>(out);

    merge_kernel<<<512, 256>>>(out);
}